// round 3
// baseline (speedup 1.0000x reference)
#include <cuda_runtime.h>
#include <math.h>

// ---------------- problem constants (fixed by the dataset) ----------------
#define NODES 100000
#define FEAT  64
#define EDGES 800000
#define SAMP  25000
#define HID   128

// ---------------- scratch (device globals; no allocation) ----------------
__device__ float d_pq[(size_t)NODES * 256];   // [n][0:128]=W1^T x + b, [n][128:256]=W2^T x
__device__ float d_agg[(size_t)NODES * 128];  // per-node max-aggregated activations
__device__ int   d_cnt[NODES];
__device__ int   d_off[NODES];
__device__ int   d_cur[NODES];
__device__ int   d_src[EDGES];
__device__ int   d_bsum[128];

// ---------------- counting sort of edges by target node ----------------
__global__ void k_zero_cnt(int n) {
    int i = blockIdx.x * blockDim.x + threadIdx.x;
    if (i < n) d_cnt[i] = 0;
}

__global__ void k_hist(const int* __restrict__ row, int E) {
    int i = blockIdx.x * blockDim.x + threadIdx.x;
    if (i < E) atomicAdd(&d_cnt[row[i]], 1);
}

__global__ void k_scan1(int n) {  // per-1024-block inclusive scan, block sums out
    __shared__ int sm[1024];
    int i = blockIdx.x * 1024 + threadIdx.x;
    int v = (i < n) ? d_cnt[i] : 0;
    sm[threadIdx.x] = v;
    __syncthreads();
    for (int d = 1; d < 1024; d <<= 1) {
        int t = 0;
        if (threadIdx.x >= d) t = sm[threadIdx.x - d];
        __syncthreads();
        if (threadIdx.x >= d) sm[threadIdx.x] += t;
        __syncthreads();
    }
    if (i < n) d_off[i] = sm[threadIdx.x];            // inclusive for now
    if (threadIdx.x == 1023) d_bsum[blockIdx.x] = sm[1023];
}

__global__ void k_scan2(int nb) {  // exclusive scan of <=128 block sums (1 block)
    __shared__ int sm[128];
    int t = threadIdx.x;
    int v = (t < nb) ? d_bsum[t] : 0;
    sm[t] = v;
    __syncthreads();
    for (int d = 1; d < 128; d <<= 1) {
        int u = 0;
        if (t >= d) u = sm[t - d];
        __syncthreads();
        if (t >= d) sm[t] += u;
        __syncthreads();
    }
    if (t < nb) d_bsum[t] = sm[t] - v;  // exclusive
}

__global__ void k_scan3(int n) {  // finalize exclusive offsets + scatter cursor
    int i = blockIdx.x * blockDim.x + threadIdx.x;
    if (i < n) {
        int e = d_off[i] - d_cnt[i] + d_bsum[i >> 10];
        d_off[i] = e;
        d_cur[i] = e;
    }
}

__global__ void k_scatter(const int* __restrict__ col, const int* __restrict__ row, int E) {
    int i = blockIdx.x * blockDim.x + threadIdx.x;
    if (i < E) {
        int t = row[i];
        int p = atomicAdd(&d_cur[t], 1);
        d_src[p] = col[i];
    }
}

// ---------------- per-node precompute GEMM: [N,64] x [64,256] ----------------
// B[k][j] = (j<128) ? W[k][j] : W[64+k][j-128]; bias b added to cols < 128.
#define GEMM_SMEM (64 * 68 * 4 + 64 * 256 * 4)

__global__ void k_gemm(const float* __restrict__ x, const float* __restrict__ Wm,
                       const float* __restrict__ bv, int N) {
    extern __shared__ float smem[];
    float* As = smem;             // [64][68] transposed: As[k*68 + m]
    float* Bs = smem + 64 * 68;   // [64][256]
    int tid = threadIdx.x;        // 256 threads
    int row0 = blockIdx.x * 64;

    // load A tile (64 rows x 64 cols), store transposed
    {
        int r = tid >> 2;
        int c0 = (tid & 3) * 4;
        bool ok = (row0 + r) < N;
        const float* xp = x + (size_t)(row0 + r) * FEAT;
#pragma unroll
        for (int i = 0; i < 4; i++) {
            int c = c0 + i * 16;
            float4 v = ok ? *(const float4*)(xp + c) : make_float4(0.f, 0.f, 0.f, 0.f);
            As[(c + 0) * 68 + r] = v.x;
            As[(c + 1) * 68 + r] = v.y;
            As[(c + 2) * 68 + r] = v.z;
            As[(c + 3) * 68 + r] = v.w;
        }
    }
    // load B tile (64 x 256) assembled from W rows [0:64) and [64:128)
    {
#pragma unroll
        for (int i = 0; i < 16; i++) {
            int v = tid + 256 * i;   // 0..4095 float4 slots
            int k = v >> 6;
            int jq = v & 63;
            const float* src = (jq < 32) ? (Wm + k * 128 + jq * 4)
                                         : (Wm + (64 + k) * 128 + (jq - 32) * 4);
            *(float4*)&Bs[k * 256 + jq * 4] = *(const float4*)src;
        }
    }
    __syncthreads();

    int tm = tid >> 5;   // 0..7  -> rows tm*8..tm*8+7
    int tn = tid & 31;   // 0..31 -> cols tn*8..tn*8+7
    float acc[8][8];
#pragma unroll
    for (int i = 0; i < 8; i++)
#pragma unroll
        for (int j = 0; j < 8; j++) acc[i][j] = 0.f;

#pragma unroll 4
    for (int k = 0; k < 64; k++) {
        float a[8], bb[8];
        *(float4*)(a)     = *(const float4*)&As[k * 68 + tm * 8];
        *(float4*)(a + 4) = *(const float4*)&As[k * 68 + tm * 8 + 4];
        *(float4*)(bb)     = *(const float4*)&Bs[k * 256 + tn * 8];
        *(float4*)(bb + 4) = *(const float4*)&Bs[k * 256 + tn * 8 + 4];
#pragma unroll
        for (int i = 0; i < 8; i++)
#pragma unroll
            for (int j = 0; j < 8; j++) acc[i][j] = fmaf(a[i], bb[j], acc[i][j]);
    }

    float bias[8];
#pragma unroll
    for (int j = 0; j < 8; j++) {
        int c = tn * 8 + j;
        bias[j] = (c < 128) ? bv[c] : 0.f;
    }
#pragma unroll
    for (int i = 0; i < 8; i++) {
        int r = row0 + tm * 8 + i;
        if (r < N) {
            float* dst = &d_pq[(size_t)r * 256 + tn * 8];
            float4 v0 = make_float4(acc[i][0] + bias[0], acc[i][1] + bias[1],
                                    acc[i][2] + bias[2], acc[i][3] + bias[3]);
            float4 v1 = make_float4(acc[i][4] + bias[4], acc[i][5] + bias[5],
                                    acc[i][6] + bias[6], acc[i][7] + bias[7]);
            *(float4*)dst = v0;
            *(float4*)(dst + 4) = v1;
        }
    }
}

// ---------------- edge aggregation: one warp per target node ----------------
__device__ __forceinline__ float angle3(float ax, float ay, float az,
                                        float bx, float by, float bz) {
    float cx = ay * bz - az * by;
    float cy = az * bx - ax * bz;
    float cz = ax * by - ay * bx;
    float cn = sqrtf(cx * cx + cy * cy + cz * cz);
    float d = ax * bx + ay * by + az * bz;
    return atan2f(cn, d);
}

__global__ void k_agg(const float* __restrict__ pos, const float* __restrict__ nor,
                      const float* __restrict__ Wm, int N) {
    int w = (blockIdx.x * blockDim.x + threadIdx.x) >> 5;
    if (w >= N) return;
    int cnt = d_cnt[w];
    if (cnt == 0) return;
    int lane = threadIdx.x & 31;
    int start = d_off[w];
    int end = start + cnt;
    int col = lane * 4;

    float4 q  = *(const float4*)&d_pq[(size_t)w * 256 + col];   // includes bias
    float4 w0 = *(const float4*)&Wm[128 * 128 + col];           // ppf weight rows
    float4 w1 = *(const float4*)&Wm[129 * 128 + col];
    float4 w2 = *(const float4*)&Wm[130 * 128 + col];
    float4 w3 = *(const float4*)&Wm[131 * 128 + col];
    float ptx = pos[3 * w], pty = pos[3 * w + 1], ptz = pos[3 * w + 2];
    float ntx = nor[3 * w], nty = nor[3 * w + 1], ntz = nor[3 * w + 2];
    float4 m = make_float4(0.f, 0.f, 0.f, 0.f);  // relu floor + empty handling

    for (int base = start; base < end; base += 32) {
        int j = base + lane;
        int s = 0;
        float f0 = 0.f, f1 = 0.f, f2 = 0.f, f3 = 0.f;
        if (j < end) {
            s = d_src[j];
            float px = pos[3 * s] - ptx;
            float py = pos[3 * s + 1] - pty;
            float pz = pos[3 * s + 2] - ptz;
            float nsx = nor[3 * s], nsy = nor[3 * s + 1], nsz = nor[3 * s + 2];
            f0 = sqrtf(px * px + py * py + pz * pz);
            f1 = angle3(ntx, nty, ntz, px, py, pz);   // angle(n1, pseudo)
            f2 = angle3(nsx, nsy, nsz, px, py, pz);   // angle(n0, pseudo)
            f3 = angle3(ntx, nty, ntz, nsx, nsy, nsz);// angle(n1, n0)
        }
        int c32 = end - base;
        if (c32 > 32) c32 = 32;
        for (int i = 0; i < c32; i++) {
            int si  = __shfl_sync(0xffffffffu, s, i);
            float g0 = __shfl_sync(0xffffffffu, f0, i);
            float g1 = __shfl_sync(0xffffffffu, f1, i);
            float g2 = __shfl_sync(0xffffffffu, f2, i);
            float g3 = __shfl_sync(0xffffffffu, f3, i);
            float4 pv = *(const float4*)&d_pq[(size_t)si * 256 + 128 + col];
            float z0 = q.x + pv.x, z1 = q.y + pv.y, z2 = q.z + pv.z, z3 = q.w + pv.w;
            z0 = fmaf(g0, w0.x, z0); z1 = fmaf(g0, w0.y, z1); z2 = fmaf(g0, w0.z, z2); z3 = fmaf(g0, w0.w, z3);
            z0 = fmaf(g1, w1.x, z0); z1 = fmaf(g1, w1.y, z1); z2 = fmaf(g1, w1.z, z2); z3 = fmaf(g1, w1.w, z3);
            z0 = fmaf(g2, w2.x, z0); z1 = fmaf(g2, w2.y, z1); z2 = fmaf(g2, w2.z, z2); z3 = fmaf(g2, w2.w, z3);
            z0 = fmaf(g3, w3.x, z0); z1 = fmaf(g3, w3.y, z1); z2 = fmaf(g3, w3.z, z2); z3 = fmaf(g3, w3.w, z3);
            m.x = fmaxf(m.x, z0); m.y = fmaxf(m.y, z1);
            m.z = fmaxf(m.z, z2); m.w = fmaxf(m.w, z3);
        }
    }
    *(float4*)&d_agg[(size_t)w * 128 + col] = m;
}

// ---------------- gather: out[s] = agg[idx[s]] (0 if no edges), pos_out ----------------
__global__ void k_gather(const float* __restrict__ pos, const int* __restrict__ idx,
                         float* __restrict__ out, int S) {
    int s = blockIdx.x;
    int h = threadIdx.x;  // 128
    int t = idx[s];
    float v = d_cnt[t] ? d_agg[(size_t)t * 128 + h] : 0.f;
    out[(size_t)s * 128 + h] = v;
    if (h < 3) out[(size_t)S * 128 + (size_t)s * 3 + h] = pos[3 * t + h];
}

// ---------------- launch ----------------
extern "C" void kernel_launch(void* const* d_in, const int* in_sizes, int n_in,
                              void* d_out, int out_size) {
    const float *x = 0, *pos = 0, *nor = 0, *Wm = 0, *bv = 0;
    const int *edge = 0, *idx = 0;
    for (int i = 0; i < n_in; i++) {
        int sz = in_sizes[i];
        if (sz == NODES * FEAT) x = (const float*)d_in[i];
        else if (sz == NODES * 3) { if (!pos) pos = (const float*)d_in[i]; else nor = (const float*)d_in[i]; }
        else if (sz == (2 * FEAT + 4) * HID) Wm = (const float*)d_in[i];
        else if (sz == HID) bv = (const float*)d_in[i];
        else if (sz == 2 * EDGES) edge = (const int*)d_in[i];
        else if (sz == SAMP) idx = (const int*)d_in[i];
    }
    const int* ecol = edge;          // e0 (sources)
    const int* erow = edge + EDGES;  // e1 (targets)

    int nb = (NODES + 1023) / 1024;

    k_zero_cnt<<<(NODES + 255) / 256, 256>>>(NODES);
    k_hist<<<(EDGES + 255) / 256, 256>>>(erow, EDGES);
    k_scan1<<<nb, 1024>>>(NODES);
    k_scan2<<<1, 128>>>(nb);
    k_scan3<<<(NODES + 255) / 256, 256>>>(NODES);
    k_scatter<<<(EDGES + 255) / 256, 256>>>(ecol, erow, EDGES);

    cudaFuncSetAttribute(k_gemm, cudaFuncAttributeMaxDynamicSharedMemorySize, GEMM_SMEM);
    k_gemm<<<(NODES + 63) / 64, 256, GEMM_SMEM>>>(x, Wm, bv, NODES);

    k_agg<<<(NODES + 7) / 8, 256>>>(pos, nor, Wm, NODES);
    k_gather<<<SAMP, 128>>>(pos, idx, (float*)d_out, SAMP);
}